// round 4
// baseline (speedup 1.0000x reference)
#include <cuda_runtime.h>
#include <math.h>

// Problem constants
#define NB 32
#define ND 64
#define NT 4096
#define NK 512
#define NTOK (NB * NT)          // 131072 tokens
#define ESTRIDE 68              // padded codebook row stride in floats

// Output layout (float32, reference tuple flattened in order):
//   [0]                     loss
//   [1 .. 1+NB*ND*NT)       quantized_ste, [B, D, T] layout
//   [1+NB*ND*NT]            perplexity
//   [2+NB*ND*NT .. +NTOK)   encoding indices (cast to float)
#define Q_OFF     ((size_t)1)
#define PERP_OFF  ((size_t)1 + (size_t)NB * ND * NT)
#define IDX_OFF   (PERP_OFF + 1)

// Cross-block scratch (no allocations allowed -> __device__ globals)
__device__ float g_loss;
__device__ unsigned int g_counts[NK];

__global__ void vq_init() {
    int i = threadIdx.x;
    if (i == 0) g_loss = 0.f;
    if (i < NK) g_counts[i] = 0u;
}

__global__ __launch_bounds__(512, 1) void vq_main(
    const float* __restrict__ in,    // [B, D, T]
    const float* __restrict__ emb,   // [K, D]
    float* __restrict__ out)
{
    extern __shared__ float smem[];
    float* sE = smem;                                  // NK*ESTRIDE floats (raw f32)
    float* sNorm = smem + NK * ESTRIDE;                // NK floats
    unsigned int* sCount = (unsigned int*)(sNorm + NK);// NK uints
    __shared__ float sLoss;

    const int tid = threadIdx.x;
    const int wid = tid >> 5;
    const int lane = tid & 31;
    if (tid == 0) sLoss = 0.f;
    if (tid < NK) sCount[tid] = 0u;

    // Stage raw f32 codebook into smem with padded stride
    const float4* e4 = (const float4*)emb;
    for (int i = tid; i < NK * (ND / 4); i += 512) {
        int k = i / (ND / 4);
        int j = i % (ND / 4);
        float4 v = e4[i];
        *(float4*)(sE + k * ESTRIDE + 4 * j) = v;
    }
    __syncthreads();

    // ||e_k||^2 — replicate XLA GPU warp row-reduction of jnp.sum(e*e, axis=1):
    //   * products are ROUNDED separately (no fma contraction),
    //   * lane l accumulates elements {l, l+32} sequentially,
    //   * then 5-level shfl_down butterfly tree (offsets 16,8,4,2,1).
    // One warp per code; 16 warps cover 512 codes in 32 sweeps.
    for (int k = wid; k < NK; k += 16) {
        const float* e = sE + k * ESTRIDE;
        float a = __fmul_rn(e[lane], e[lane]);
        float b = __fmul_rn(e[lane + 32], e[lane + 32]);
        float acc = __fadd_rn(a, b);
        #pragma unroll
        for (int off = 16; off; off >>= 1)
            acc = __fadd_rn(acc, __shfl_down_sync(0xffffffffu, acc, off));
        if (lane == 0) sNorm[k] = acc;
    }
    __syncthreads();

    // One token per thread
    const int token = blockIdx.x * 512 + tid;
    const int b = token >> 12;          // token / NT
    const int t = token & (NT - 1);     // token % NT

    const float* xp = in + (size_t)b * ND * NT + t;
    float x[ND];
    #pragma unroll
    for (int d = 0; d < ND; d++)
        x[d] = xp[(size_t)d * NT];      // coalesced across threads (consecutive t)

    // ||x||^2 — replicate XLA GPU column-reduction (D is strided in [B,D,T]):
    // sequential ascending, NO fma contraction (separate fmul + fadd).
    float xn = 0.f;
    #pragma unroll
    for (int d = 0; d < ND; d++)
        xn = __fadd_rn(xn, __fmul_rn(x[d], x[d]));

    // Argmin over codes:
    //   d_k = fl( fl(xn + en_k) - 2 * dot_k ),
    //   dot_k = sequential single-accumulator fmaf ascending (SGEMM K-chain).
    // 4 codes in flight -> 4 independent FFMA chains for ILP.
    float best = 3.402823466e38f;
    int bidx = 0;
    for (int k0 = 0; k0 < NK; k0 += 4) {
        const float4* e0 = (const float4*)(sE + (k0 + 0) * ESTRIDE);
        const float4* e1 = (const float4*)(sE + (k0 + 1) * ESTRIDE);
        const float4* e2 = (const float4*)(sE + (k0 + 2) * ESTRIDE);
        const float4* e3 = (const float4*)(sE + (k0 + 3) * ESTRIDE);
        float a0 = 0.f, a1 = 0.f, a2 = 0.f, a3 = 0.f;
        #pragma unroll
        for (int j = 0; j < ND / 4; j++) {
            float4 v0 = e0[j], v1 = e1[j], v2 = e2[j], v3 = e3[j];
            a0 = __fmaf_rn(x[4*j+0], v0.x, a0);
            a1 = __fmaf_rn(x[4*j+0], v1.x, a1);
            a2 = __fmaf_rn(x[4*j+0], v2.x, a2);
            a3 = __fmaf_rn(x[4*j+0], v3.x, a3);
            a0 = __fmaf_rn(x[4*j+1], v0.y, a0);
            a1 = __fmaf_rn(x[4*j+1], v1.y, a1);
            a2 = __fmaf_rn(x[4*j+1], v2.y, a2);
            a3 = __fmaf_rn(x[4*j+1], v3.y, a3);
            a0 = __fmaf_rn(x[4*j+2], v0.z, a0);
            a1 = __fmaf_rn(x[4*j+2], v1.z, a1);
            a2 = __fmaf_rn(x[4*j+2], v2.z, a2);
            a3 = __fmaf_rn(x[4*j+2], v3.z, a3);
            a0 = __fmaf_rn(x[4*j+3], v0.w, a0);
            a1 = __fmaf_rn(x[4*j+3], v1.w, a1);
            a2 = __fmaf_rn(x[4*j+3], v2.w, a2);
            a3 = __fmaf_rn(x[4*j+3], v3.w, a3);
        }
        float d0 = __fadd_rn(__fadd_rn(xn, sNorm[k0 + 0]), __fmul_rn(-2.f, a0));
        float d1 = __fadd_rn(__fadd_rn(xn, sNorm[k0 + 1]), __fmul_rn(-2.f, a1));
        float d2 = __fadd_rn(__fadd_rn(xn, sNorm[k0 + 2]), __fmul_rn(-2.f, a2));
        float d3 = __fadd_rn(__fadd_rn(xn, sNorm[k0 + 3]), __fmul_rn(-2.f, a3));
        // strict < keeps first-min (jnp.argmin tie rule)
        if (d0 < best) { best = d0; bidx = k0 + 0; }
        if (d1 < best) { best = d1; bidx = k0 + 1; }
        if (d2 < best) { best = d2; bidx = k0 + 2; }
        if (d3 < best) { best = d3; bidx = k0 + 3; }
    }

    // Index output (as float)
    out[IDX_OFF + (size_t)token] = (float)bidx;

    // Histogram (smem, flushed below)
    atomicAdd(&sCount[bidx], 1u);

    // Quantized output: gather chosen code (smem), write back in [B, D, T] layout.
    // Loss from true values: sum (q - x)^2.
    const float* eb = sE + bidx * ESTRIDE;
    float* qp = out + Q_OFF + (size_t)b * ND * NT + t;
    float lsum = 0.f;
    #pragma unroll
    for (int d = 0; d < ND; d++) {
        float v = eb[d];
        qp[(size_t)d * NT] = v;
        float df = v - x[d];
        lsum = __fmaf_rn(df, df, lsum);
    }

    #pragma unroll
    for (int off = 16; off; off >>= 1)
        lsum += __shfl_down_sync(0xffffffffu, lsum, off);
    if (lane == 0) atomicAdd(&sLoss, lsum);
    __syncthreads();
    if (tid == 0) atomicAdd(&g_loss, sLoss);

    if (tid < NK) {
        unsigned c = sCount[tid];
        if (c) atomicAdd(&g_counts[tid], c);
    }
}

__global__ void vq_final(float* __restrict__ out) {
    __shared__ float red[32];
    int tid = threadIdx.x;   // 512 threads, one per code
    if (tid < 32) red[tid] = 0.f;
    __syncthreads();

    unsigned c = g_counts[tid];
    float p = (float)c / (float)NTOK;
    float term = p * logf(p + 1e-10f);

    #pragma unroll
    for (int off = 16; off; off >>= 1)
        term += __shfl_down_sync(0xffffffffu, term, off);
    if ((tid & 31) == 0) red[tid >> 5] = term;
    __syncthreads();

    if (tid < 32) {
        float v = red[tid];
        #pragma unroll
        for (int off = 16; off; off >>= 1)
            v += __shfl_down_sync(0xffffffffu, v, off);
        if (tid == 0) {
            out[PERP_OFF] = expf(-v);
            out[0] = 0.25f * g_loss / (float)((size_t)NTOK * ND);
        }
    }
}

extern "C" void kernel_launch(void* const* d_in, const int* in_sizes, int n_in,
                              void* d_out, int out_size) {
    const float* in  = (const float*)d_in[0];   // inputs [32, 64, 4096]
    const float* emb = (const float*)d_in[1];   // embedding [512, 64]
    float* out = (float*)d_out;

    size_t smem = (size_t)(NK * ESTRIDE + NK) * sizeof(float) + NK * sizeof(unsigned int);
    cudaFuncSetAttribute(vq_main, cudaFuncAttributeMaxDynamicSharedMemorySize, (int)smem);

    vq_init<<<1, 512>>>();
    vq_main<<<NTOK / 512, 512, smem>>>(in, emb, out);
    vq_final<<<1, 512>>>(out);
}

// round 5
// speedup vs baseline: 1.2521x; 1.2521x over previous
#include <cuda_runtime.h>
#include <math.h>

// Problem constants
#define NB 32
#define ND 64
#define NT 4096
#define NK 512
#define NTOK (NB * NT)          // 131072 tokens
#define NCTA 148                // one CTA per SM, balanced chunks

// Output layout (float32, reference tuple flattened in order):
#define Q_OFF     ((size_t)1)
#define PERP_OFF  ((size_t)1 + (size_t)NB * ND * NT)
#define IDX_OFF   (PERP_OFF + 1)

// Cross-block scratch (no allocations allowed -> __device__ globals)
__device__ float g_loss;
__device__ unsigned int g_counts[NK];

// Packed dual-FMA: each 32-bit half is an independent IEEE fma.rn.f32 —
// bitwise identical to the scalar chain per code. (Blackwell f32x2)
__device__ __forceinline__ void fma2(unsigned long long& a,
                                     unsigned long long x,
                                     unsigned long long e) {
    asm("fma.rn.f32x2 %0, %1, %2, %0;" : "+l"(a) : "l"(x), "l"(e));
}
__device__ __forceinline__ unsigned long long pack2(float v) {
    unsigned long long r;
    asm("mov.b64 %0, {%1, %1};" : "=l"(r) : "f"(v));
    return r;
}
__device__ __forceinline__ void unpack2(unsigned long long a, float& lo, float& hi) {
    asm("mov.b64 {%0, %1}, %2;" : "=f"(lo), "=f"(hi) : "l"(a));
}

__global__ void vq_init() {
    int i = threadIdx.x;
    if (i == 0) g_loss = 0.f;
    if (i < NK) g_counts[i] = 0u;
}

__global__ __launch_bounds__(512, 1) void vq_main(
    const float* __restrict__ in,    // [B, D, T]
    const float* __restrict__ emb,   // [K, D]
    float* __restrict__ out)
{
    // smem: packed code pairs. Pair p holds codes {2p, 2p+1}:
    //   sE2[p*64 + d] = float2( e_{2p}[d], e_{2p+1}[d] )
    // One LDS.128 (ulonglong2) yields packed operands for d and d+1.
    extern __shared__ float smem[];
    float2* sE2 = (float2*)smem;                         // 256*64 float2 = 128KB
    float* sNorm = smem + NK * ND;                       // NK floats
    unsigned int* sCount = (unsigned int*)(sNorm + NK);  // NK uints
    __shared__ float sLoss;

    const int tid = threadIdx.x;
    const int wid = tid >> 5;
    const int lane = tid & 31;
    if (tid == 0) sLoss = 0.f;
    if (tid < NK) sCount[tid] = 0u;

    // Stage packed codebook pairs
    for (int i = tid; i < NK / 2 * ND; i += 512) {
        int p = i >> 6;          // pair
        int d = i & 63;
        sE2[i] = make_float2(emb[(2 * p) * ND + d], emb[(2 * p + 1) * ND + d]);
    }

    // ||e_k||^2 — FROZEN numerics (matches reference): no-fma products,
    // lane l sums {l, l+32}, then shfl_down tree 16,8,4,2,1.
    for (int k = wid; k < NK; k += 16) {
        const float* e = emb + k * ND;
        float a = __fmul_rn(e[lane], e[lane]);
        float b = __fmul_rn(e[lane + 32], e[lane + 32]);
        float acc = __fadd_rn(a, b);
        #pragma unroll
        for (int off = 16; off; off >>= 1)
            acc = __fadd_rn(acc, __shfl_down_sync(0xffffffffu, acc, off));
        if (lane == 0) sNorm[k] = acc;
    }
    __syncthreads();

    // Balanced contiguous chunks: first 92 CTAs get 886 tokens, rest 885.
    const int cta = blockIdx.x;
    const int base = cta * 885 + min(cta, 92);
    const int count = (cta < 92) ? 886 : 885;

    float llocal = 0.f;

    for (int tk = tid; tk < count; tk += 512) {
        const int token = base + tk;
        const int b = token >> 12;
        const int t = token & (NT - 1);

        const float* xp = in + (size_t)b * ND * NT + t;
        float x[ND];
        #pragma unroll
        for (int d = 0; d < ND; d++)
            x[d] = xp[(size_t)d * NT];

        // ||x||^2 — FROZEN: sequential ascending, no fma contraction.
        float xn = 0.f;
        #pragma unroll
        for (int d = 0; d < ND; d++)
            xn = __fadd_rn(xn, __fmul_rn(x[d], x[d]));

        // Argmin. Per code: exact sequential-ascending f32 FMA chain
        // (each f32x2 half == scalar fma.rn chain). 8 codes (4 pairs) in flight.
        float best = 3.402823466e38f;
        int bidx = 0;
        #pragma unroll 1
        for (int k0 = 0; k0 < NK; k0 += 8) {
            const int q = k0 >> 1;  // first pair index
            const ulonglong2* P0 = (const ulonglong2*)(sE2 + (q + 0) * ND);
            const ulonglong2* P1 = (const ulonglong2*)(sE2 + (q + 1) * ND);
            const ulonglong2* P2 = (const ulonglong2*)(sE2 + (q + 2) * ND);
            const ulonglong2* P3 = (const ulonglong2*)(sE2 + (q + 3) * ND);
            unsigned long long a0 = 0ull, a1 = 0ull, a2 = 0ull, a3 = 0ull;
            #pragma unroll
            for (int d2 = 0; d2 < ND / 2; d2++) {
                ulonglong2 w0 = P0[d2];
                ulonglong2 w1 = P1[d2];
                ulonglong2 w2 = P2[d2];
                ulonglong2 w3 = P3[d2];
                unsigned long long xlo = pack2(x[2 * d2 + 0]);
                unsigned long long xhi = pack2(x[2 * d2 + 1]);
                // d = 2*d2 first, then 2*d2+1 (ascending order per chain)
                fma2(a0, xlo, w0.x); fma2(a1, xlo, w1.x);
                fma2(a2, xlo, w2.x); fma2(a3, xlo, w3.x);
                fma2(a0, xhi, w0.y); fma2(a1, xhi, w1.y);
                fma2(a2, xhi, w2.y); fma2(a3, xhi, w3.y);
            }
            float dot[8];
            unpack2(a0, dot[0], dot[1]);
            unpack2(a1, dot[2], dot[3]);
            unpack2(a2, dot[4], dot[5]);
            unpack2(a3, dot[6], dot[7]);
            #pragma unroll
            for (int j = 0; j < 8; j++) {
                // FROZEN combine: fl( fl(xn + en) + fl(-2*dot) )
                float dst = __fadd_rn(__fadd_rn(xn, sNorm[k0 + j]),
                                      __fmul_rn(-2.f, dot[j]));
                if (dst < best) { best = dst; bidx = k0 + j; }  // first-min
            }
        }

        // Index output (as float)
        out[IDX_OFF + (size_t)token] = (float)bidx;

        // Histogram
        atomicAdd(&sCount[bidx], 1u);

        // Quantized output: gather original f32 code row (gmem, L1-hot),
        // write back in [B, D, T] layout; loss from true values.
        const float4* eb4 = (const float4*)(emb + bidx * ND);
        float* qp = out + Q_OFF + (size_t)b * ND * NT + t;
        #pragma unroll
        for (int j = 0; j < ND / 4; j++) {
            float4 v = eb4[j];
            qp[(size_t)(4 * j + 0) * NT] = v.x;
            qp[(size_t)(4 * j + 1) * NT] = v.y;
            qp[(size_t)(4 * j + 2) * NT] = v.z;
            qp[(size_t)(4 * j + 3) * NT] = v.w;
            float t0 = v.x - x[4 * j + 0];
            float t1 = v.y - x[4 * j + 1];
            float t2 = v.z - x[4 * j + 2];
            float t3 = v.w - x[4 * j + 3];
            llocal = __fmaf_rn(t0, t0, llocal);
            llocal = __fmaf_rn(t1, t1, llocal);
            llocal = __fmaf_rn(t2, t2, llocal);
            llocal = __fmaf_rn(t3, t3, llocal);
        }
    }

    // Block loss reduction (all 512 threads present; idle ones carry 0)
    float lsum = llocal;
    #pragma unroll
    for (int off = 16; off; off >>= 1)
        lsum += __shfl_down_sync(0xffffffffu, lsum, off);
    if (lane == 0) atomicAdd(&sLoss, lsum);
    __syncthreads();
    if (tid == 0) atomicAdd(&g_loss, sLoss);

    if (tid < NK) {
        unsigned c = sCount[tid];
        if (c) atomicAdd(&g_counts[tid], c);
    }
}

__global__ void vq_final(float* __restrict__ out) {
    __shared__ float red[32];
    int tid = threadIdx.x;   // 512 threads, one per code
    if (tid < 32) red[tid] = 0.f;
    __syncthreads();

    unsigned c = g_counts[tid];
    float p = (float)c / (float)NTOK;
    float term = p * logf(p + 1e-10f);

    #pragma unroll
    for (int off = 16; off; off >>= 1)
        term += __shfl_down_sync(0xffffffffu, term, off);
    if ((tid & 31) == 0) red[tid >> 5] = term;
    __syncthreads();

    if (tid < 32) {
        float v = red[tid];
        #pragma unroll
        for (int off = 16; off; off >>= 1)
            v += __shfl_down_sync(0xffffffffu, v, off);
        if (tid == 0) {
            out[PERP_OFF] = expf(-v);
            out[0] = 0.25f * g_loss / (float)((size_t)NTOK * ND);
        }
    }
}

extern "C" void kernel_launch(void* const* d_in, const int* in_sizes, int n_in,
                              void* d_out, int out_size) {
    const float* in  = (const float*)d_in[0];   // inputs [32, 64, 4096]
    const float* emb = (const float*)d_in[1];   // embedding [512, 64]
    float* out = (float*)d_out;

    size_t smem = (size_t)(NK * ND + NK) * sizeof(float) + NK * sizeof(unsigned int);
    cudaFuncSetAttribute(vq_main, cudaFuncAttributeMaxDynamicSharedMemorySize, (int)smem);

    vq_init<<<1, 512>>>();
    vq_main<<<NCTA, 512, smem>>>(in, emb, out);
    vq_final<<<1, 512>>>(out);
}